// round 1
// baseline (speedup 1.0000x reference)
#include <cuda_runtime.h>
#include <cub/block/block_radix_sort.cuh>

// SoftArgsortTopK: scores [B=128, R=8192] f32, ref_class [R] i32, k=32 (K unused).
// Key insight: with REG_STRENGTH=0.01, the isotonic projection is the identity
// (w decreases by 100/step, score gaps << 100), so soft_sort == exact sort,
// up to the reference's float quantization yk = fl(fl(w + x) - w) with
// w = (k - j)/0.01, which we replicate exactly with round-to-nearest intrinsics.
//
// Output layout (out_size = 2*B*k): [0, B*k) = yk row-major, [B*k, 2*B*k) = labels.

constexpr int R_ = 8192;
constexpr int TK = 32;    // k
constexpr int NT = 512;   // threads per block
constexpr int IT = R_ / NT;  // 16 items per thread
constexpr int NW = NT / 32;  // 16 warps

__global__ void __launch_bounds__(NT, 1)
soft_argsort_topk_kernel(const float* __restrict__ scores,
                         const int*   __restrict__ ref_class,
                         float* __restrict__ yk_out,
                         float* __restrict__ lbl_out)
{
    using Sorter = cub::BlockRadixSort<float, NT, IT>;

    __shared__ union {
        typename Sorter::TempStorage sort;
        struct {
            float pnum[TK][NW];
            float pden[TK][NW];
        } red;
    } shm;
    __shared__ float y_s[TK], A_s[TK], B_s[TK];

    const int b   = blockIdx.x;
    const int tid = threadIdx.x;
    const float* row = scores + (size_t)b * R_;

    // ---- Phase 1: exact ascending sort of the row (top-32 = tail) ----
    float items[IT];
    {
        // Each thread owns 16 consecutive floats -> 4x float4 loads.
        const float4* row4 = reinterpret_cast<const float4*>(row) + tid * (IT / 4);
#pragma unroll
        for (int q = 0; q < IT / 4; q++) {
            float4 v = row4[q];
            items[q * 4 + 0] = v.x;
            items[q * 4 + 1] = v.y;
            items[q * 4 + 2] = v.z;
            items[q * 4 + 3] = v.w;
        }
    }
    Sorter(shm.sort).Sort(items);  // blocked arrangement, ascending

    // Threads holding the global tail write the top-32 (ascending) to smem.
#pragma unroll
    for (int i = 0; i < IT; i++) {
        int idx = tid * IT + i;
        if (idx >= R_ - TK) y_s[idx - (R_ - TK)] = items[i];
    }
    __syncthreads();

    if (tid < TK) {
        // Replicate the reference's quantization: yk = fl(fl(w + x) - w),
        // w = (k - j) / 0.01f (IEEE rn, no contraction).
        float x = y_s[tid];
        float w = __fdiv_rn((float)(TK - tid), 0.01f);
        float y = __fsub_rn(__fadd_rn(w, x), w);
        yk_out[b * TK + tid] = y;
        A_s[tid] = __expf(-10.0f * y);
        B_s[tid] = __expf( 10.0f * y);
        y_s[tid] = y;
    }
    __syncthreads();

    // ---- Phase 2: soft labels ----
    // exp(-10|s - y|) = min( exp(10 s)*exp(-10 y), exp(-10 s)*exp(10 y) ).
    // Overflow in the discarded branch (inf) is absorbed by fminf.
    float ea[IT], eb[IT], rcf[IT];
#pragma unroll
    for (int i = 0; i < IT; i++) {
        float s = row[tid + i * NT];                       // coalesced
        ea[i]  = __expf( 10.0f * s);
        eb[i]  = __expf(-10.0f * s);
        rcf[i] = (float)ref_class[tid + i * NT];
    }

    const int warp = tid >> 5, lane = tid & 31;
#pragma unroll 4
    for (int j = 0; j < TK; j++) {
        const float A  = A_s[j];
        const float Bv = B_s[j];
        float den = 0.0f, num = 0.0f;
#pragma unroll
        for (int i = 0; i < IT; i++) {
            float e = fminf(ea[i] * A, eb[i] * Bv);
            den += e;
            num = fmaf(e, rcf[i], num);
        }
#pragma unroll
        for (int o = 16; o; o >>= 1) {
            den += __shfl_xor_sync(0xffffffffu, den, o);
            num += __shfl_xor_sync(0xffffffffu, num, o);
        }
        if (lane == 0) {
            shm.red.pden[j][warp] = den;
            shm.red.pnum[j][warp] = num;
        }
    }
    __syncthreads();

    if (tid < TK) {
        float den = 0.0f, num = 0.0f;
#pragma unroll
        for (int w = 0; w < NW; w++) {
            den += shm.red.pden[tid][w];
            num += shm.red.pnum[tid][w];
        }
        lbl_out[b * TK + tid] = num / den;
    }
}

extern "C" void kernel_launch(void* const* d_in, const int* in_sizes, int n_in,
                              void* d_out, int out_size)
{
    const float* scores    = (const float*)d_in[0];
    const int*   ref_class = (const int*)d_in[1];
    const int R = in_sizes[1];           // 8192
    const int B = in_sizes[0] / R;       // 128

    float* yk_out  = (float*)d_out;
    float* lbl_out = (float*)d_out + (size_t)B * TK;

    soft_argsort_topk_kernel<<<B, NT>>>(scores, ref_class, yk_out, lbl_out);
}

// round 3
// speedup vs baseline: 1.1390x; 1.1390x over previous
#include <cuda_runtime.h>

// SoftArgsortTopK: scores [B=128, R=8192] f32, ref_class [R] i32, k=32.
// Isotonic projection is the identity for reg=0.01 (w steps by 100 >> score gaps),
// so soft_sort == exact sort up to the reference's quantization
// yk = fl(fl(w + x) - w), w = (k - j)/0.01, replicated with rn intrinsics.
// We only need the top-32, so: histogram radix-select + warp argmax extraction
// instead of a full 8192-key radix sort.
//
// Output: [0, B*k) = yk row-major, [B*k, 2*B*k) = soft labels.

constexpr int R_ = 8192;
constexpr int TK = 32;       // k
constexpr int NT = 512;      // threads per block
constexpr int IT = R_ / NT;  // 16 items per thread (blocked)
constexpr int NW = NT / 32;  // 16 warps

__device__ __forceinline__ unsigned fkey(float x) {
    // monotonic (ascending) unsigned key for float compare
    unsigned u = __float_as_uint(x);
    return u ^ (unsigned)(((int)u >> 31) | 0x80000000);
}

__global__ void __launch_bounds__(NT, 1)
soft_argsort_topk_kernel(const float* __restrict__ scores,
                         const int*   __restrict__ ref_class,
                         float* __restrict__ yk_out,
                         float* __restrict__ lbl_out)
{
    __shared__ int   hist[256];
    __shared__ float buf[R_];            // candidate buffer (worst case = whole row)
    __shared__ int   s_T, s_cnt;
    __shared__ float A_s[TK], B_s[TK];
    __shared__ float pnum[TK][NW], pden[TK][NW];

    const int b   = blockIdx.x;
    const int tid = threadIdx.x;
    const float* row = scores + (size_t)b * R_;

    if (tid < 256) hist[tid] = 0;
    if (tid == 0)  s_cnt = 0;

    // ---- load row into registers (blocked, float4) ----
    float items[IT];
    {
        const float4* row4 = reinterpret_cast<const float4*>(row) + tid * (IT / 4);
#pragma unroll
        for (int q = 0; q < IT / 4; q++) {
            float4 v = row4[q];
            items[4*q+0] = v.x; items[4*q+1] = v.y;
            items[4*q+2] = v.z; items[4*q+3] = v.w;
        }
    }
    __syncthreads();

    // ---- Pass 1: 256-bin histogram on top byte of key ----
#pragma unroll
    for (int i = 0; i < IT; i++)
        atomicAdd(&hist[fkey(items[i]) >> 24], 1);
    __syncthreads();

    // ---- warp 0: suffix-scan from the top to find threshold bin T ----
    // T = highest bin where (count strictly above) < 32 <= (count incl. bin)
    if (tid < 32) {
        const int base = tid * 8;
        int h[8], g = 0;
#pragma unroll
        for (int j = 0; j < 8; j++) { h[j] = hist[base + j]; g += h[j]; }
        int s = g;  // inclusive suffix sum over lane groups
#pragma unroll
        for (int o = 1; o < 32; o <<= 1) {
            int t = __shfl_down_sync(0xffffffffu, s, o);
            if (tid < 32 - o) s += t;
        }
        int run = s - g;  // count in groups strictly above this lane's group
#pragma unroll
        for (int j = 7; j >= 0; j--) {
            if (run < TK && run + h[j] >= TK) s_T = base + j;
            run += h[j];
        }
    }
    __syncthreads();

    // ---- gather candidates (key byte >= T) into smem buffer ----
    {
        const unsigned T = (unsigned)s_T;
#pragma unroll
        for (int i = 0; i < IT; i++) {
            if ((fkey(items[i]) >> 24) >= T) {
                int p = atomicAdd(&s_cnt, 1);
                buf[p] = items[i];
            }
        }
    }
    __syncthreads();

    // ---- warp 0: extract top-32 by repeated warp argmax;
    //      meanwhile warps 1..15 start the exp precompute below ----
    if (tid < 32) {
        const float NEG = __int_as_float(0xff800000);  // -inf
        const int c = s_cnt;                            // >= 32 by construction
        float my = 0.0f;
#pragma unroll 1
        for (int j = 0; j < TK; j++) {                  // j-th largest
            float v = NEG; int idx = -1;
            for (int p = tid; p < c; p += 32) {
                float x = buf[p];
                if (x > v) { v = x; idx = p; }
            }
#pragma unroll
            for (int o = 16; o; o >>= 1) {
                float ov = __shfl_xor_sync(0xffffffffu, v, o);
                int   oi = __shfl_xor_sync(0xffffffffu, idx, o);
                if (ov > v || (ov == v && (unsigned)oi < (unsigned)idx)) { v = ov; idx = oi; }
            }
            if (tid == 0) buf[idx] = NEG;               // remove one copy
            __syncwarp();
            if (tid == TK - 1 - j) my = v;              // ascending position
        }
        // reference quantization: yk = fl(fl(w + x) - w), w = (k - lane)/0.01
        float w = __fdiv_rn((float)(TK - tid), 0.01f);
        float y = __fsub_rn(__fadd_rn(w, my), w);
        yk_out[b * TK + tid] = y;
        A_s[tid] = __expf(-10.0f * y);
        B_s[tid] = __expf( 10.0f * y);
    }

    // ---- all warps: exp precompute (overlaps warp-0 extraction) ----
    // exp(-10|s-y|) = min( exp(10s)*exp(-10y), exp(-10s)*exp(10y) )
    float ea[IT], eb[IT], rcf[IT];
    {
        const int4* rci = reinterpret_cast<const int4*>(ref_class) + tid * (IT / 4);
#pragma unroll
        for (int q = 0; q < IT / 4; q++) {
            int4 rv = rci[q];
            rcf[4*q+0] = (float)rv.x; rcf[4*q+1] = (float)rv.y;
            rcf[4*q+2] = (float)rv.z; rcf[4*q+3] = (float)rv.w;
        }
#pragma unroll
        for (int i = 0; i < IT; i++) {
            ea[i] = __expf( 10.0f * items[i]);
            eb[i] = __expf(-10.0f * items[i]);
        }
    }
    __syncthreads();

    // ---- main softmax-label loop ----
    const int warp = tid >> 5, lane = tid & 31;
#pragma unroll 4
    for (int j = 0; j < TK; j++) {
        const float A  = A_s[j];
        const float Bv = B_s[j];
        float den = 0.0f, num = 0.0f;
#pragma unroll
        for (int i = 0; i < IT; i++) {
            float e = fminf(ea[i] * A, eb[i] * Bv);
            den += e;
            num = fmaf(e, rcf[i], num);
        }
#pragma unroll
        for (int o = 16; o; o >>= 1) {
            den += __shfl_xor_sync(0xffffffffu, den, o);
            num += __shfl_xor_sync(0xffffffffu, num, o);
        }
        if (lane == 0) { pden[j][warp] = den; pnum[j][warp] = num; }
    }
    __syncthreads();

    if (tid < TK) {
        float den = 0.0f, num = 0.0f;
#pragma unroll
        for (int w = 0; w < NW; w++) { den += pden[tid][w]; num += pnum[tid][w]; }
        lbl_out[b * TK + tid] = num / den;
    }
}

extern "C" void kernel_launch(void* const* d_in, const int* in_sizes, int n_in,
                              void* d_out, int out_size)
{
    const float* scores    = (const float*)d_in[0];
    const int*   ref_class = (const int*)d_in[1];
    const int R = in_sizes[1];           // 8192
    const int B = in_sizes[0] / R;       // 128

    float* yk_out  = (float*)d_out;
    float* lbl_out = (float*)d_out + (size_t)B * TK;

    soft_argsort_topk_kernel<<<B, NT>>>(scores, ref_class, yk_out, lbl_out);
}

// round 9
// speedup vs baseline: 2.3956x; 2.1032x over previous
#include <cuda_runtime.h>

// SoftArgsortTopK: scores [B=128, R=8192] f32, ref_class [R] i32, k=32.
// Isotonic projection is identity for reg=0.01 => soft_sort == exact sort,
// up to reference quantization yk = fl(fl(w+x)-w), w=(k-j)/0.01 (replicated).
//
// Fast path:
//   1. 256-bin histogram on top key byte -> small candidate set (c ~ 190)
//   2. all-pairs rank select over candidates -> exact top-32 (parallel)
//   3. labels via split sum: for s <= y_j, exp(-10|s-y_j|) = exp(10s)*exp(-10y_j).
//      All non-candidates satisfy s < y_j for every j, so one O(R) pass gives
//      Sea = sum(exp(10s)), Src = sum(exp(10s)*rc); per-j corrections only over
//      the candidate list. O(R*K) -> O(R) + O(c*K).
//
// Output: [0, B*k) = yk row-major, [B*k, 2*B*k) = soft labels.

constexpr int R_  = 8192;
constexpr int TK  = 32;       // k
constexpr int NT  = 512;      // threads per block
constexpr int IT  = R_ / NT;  // 16 items per thread
constexpr int NW  = NT / 32;  // 16 warps
constexpr int CAP = 4096;     // candidate buffer capacity

__device__ __forceinline__ unsigned fkey(float x) {
    // monotonic (ascending) unsigned key for float compare
    unsigned u = __float_as_uint(x);
    return u ^ (unsigned)(((int)u >> 31) | 0x80000000);
}

__global__ void __launch_bounds__(NT, 1)
soft_argsort_topk_kernel(const float* __restrict__ scores,
                         const int*   __restrict__ ref_class,
                         float* __restrict__ yk_out,
                         float* __restrict__ lbl_out)
{
    __shared__ int   hist[256];
    __shared__ float cx[CAP];            // candidate values
    __shared__ float crc[CAP];           // candidate ref_class (as float)
    __shared__ int   s_T, s_cnt;
    __shared__ float y_raw[TK];
    __shared__ float A_s[TK], B_s[TK];   // exp(-10 y), exp(+10 y)
    __shared__ float pSea[NW], pSrc[NW];
    __shared__ float corr_den[TK], corr_num[TK];

    const int b    = blockIdx.x;
    const int tid  = threadIdx.x;
    const int warp = tid >> 5, lane = tid & 31;
    const float* row = scores + (size_t)b * R_;

    if (tid < 256) hist[tid] = 0;
    if (tid == 0)  s_cnt = 0;

    // ---- load row + ref_class into registers (vectorized, coalesced) ----
    float items[IT], rcf[IT];
    {
        const float4* r4 = reinterpret_cast<const float4*>(row) + tid * (IT / 4);
        const int4*   c4 = reinterpret_cast<const int4*>(ref_class) + tid * (IT / 4);
#pragma unroll
        for (int q = 0; q < IT / 4; q++) {
            float4 v = r4[q];
            int4   w = c4[q];
            items[4*q+0] = v.x; items[4*q+1] = v.y;
            items[4*q+2] = v.z; items[4*q+3] = v.w;
            rcf[4*q+0] = (float)w.x; rcf[4*q+1] = (float)w.y;
            rcf[4*q+2] = (float)w.z; rcf[4*q+3] = (float)w.w;
        }
    }
    __syncthreads();

    // ---- histogram on top key byte ----
#pragma unroll
    for (int i = 0; i < IT; i++)
        atomicAdd(&hist[fkey(items[i]) >> 24], 1);
    __syncthreads();

    // ---- warp 0: find threshold byte T.
    // Base rule: T = highest byte with suffix count >= TK.
    // CAP guard: if suffix count at T would exceed CAP, raise T (keep suffix
    // <= CAP) as long as suffix stays >= TK; candidates outside remain s < y_j
    // for all j only when excluded bins are strictly below every selected y,
    // which holds because we only ever exclude bins BELOW bins that already
    // contain >= TK elements.
    if (tid < 32) {
        const int base = tid * 8;
        int h[8], g = 0;
#pragma unroll
        for (int j = 0; j < 8; j++) { h[j] = hist[base + j]; g += h[j]; }
        int s = g;  // inclusive suffix sum over 8-bin groups
#pragma unroll
        for (int o = 1; o < 32; o <<= 1) {
            int t = __shfl_down_sync(0xffffffffu, s, o);
            if (tid < 32 - o) s += t;
        }
        int run = s - g;  // count strictly above this lane's group
#pragma unroll
        for (int j = 7; j >= 0; j--) {
            int inc = run + h[j];
            // pick the LOWEST byte such that suffix >= TK and suffix <= CAP;
            // if no byte satisfies suffix <= CAP (massive ties), pick the
            // highest byte with suffix >= TK that minimizes overflow.
            if (run < TK && inc >= TK) {
                // default selection (suffix >= TK reached exactly here)
                if (inc <= CAP) s_T = base + j;
                else            s_T = base + j;  // overflow case: clamp below
            } else if (inc > TK && inc <= CAP && run < TK) {
                s_T = base + j;
            }
            run += h[j];
        }
    }
    __syncthreads();

    // If the chosen bin overflows CAP, raise T until the suffix fits (but keep
    // suffix >= TK). Rare path; single thread, reads smem hist.
    if (tid == 0) {
        int T = s_T;
        int suf = 0;
        for (int j = 255; j >= T; j--) suf += hist[j];
        while (suf > CAP) {
            int suf2 = suf - hist[T];
            if (suf2 < TK) break;       // cannot shrink further; accept clamp
            suf = suf2; T++;
        }
        s_T = T;
    }
    __syncthreads();

    // ---- gather candidates; simultaneously accumulate base sums over
    //      non-candidates: Sea = sum(exp(10s)), Src = sum(exp(10s)*rc) ----
    {
        const unsigned T = (unsigned)s_T;
        float Sea = 0.0f, Src = 0.0f;
#pragma unroll
        for (int i = 0; i < IT; i++) {
            float s  = items[i];
            float ea = __expf(10.0f * s);
            if ((fkey(s) >> 24) >= T) {
                int p = atomicAdd(&s_cnt, 1);
                if (p < CAP) { cx[p] = s; crc[p] = rcf[i]; }
            } else {
                Sea += ea;
                Src  = fmaf(ea, rcf[i], Src);
            }
        }
#pragma unroll
        for (int o = 16; o; o >>= 1) {
            Sea += __shfl_xor_sync(0xffffffffu, Sea, o);
            Src += __shfl_xor_sync(0xffffffffu, Src, o);
        }
        if (lane == 0) { pSea[warp] = Sea; pSrc[warp] = Src; }
    }
    __syncthreads();

    const int c = min(s_cnt, CAP);

    // ---- parallel rank-select: exact top-32 (ties broken by buffer index;
    //      tie copies carry equal values, so the selected multiset is exact) ----
    for (int t = tid; t < c; t += NT) {
        float x = cx[t];
        int rank = 0;
        for (int i = 0; i < c; i++) {          // broadcast LDS, conflict-free
            float xi = cx[i];
            rank += (xi > x) || (xi == x && i < t);
        }
        if (rank < TK) y_raw[TK - 1 - rank] = x;   // ascending order
    }
    __syncthreads();

    // ---- quantize per reference; precompute exp(+-10 y) ----
    if (tid < TK) {
        float x = y_raw[tid];
        float w = __fdiv_rn((float)(TK - tid), 0.01f);
        float y = __fsub_rn(__fadd_rn(w, x), w);
        yk_out[b * TK + tid] = y;
        A_s[tid] = __expf(-10.0f * y);
        B_s[tid] = __expf( 10.0f * y);
    }
    __syncthreads();

    // ---- per-j corrections over candidates: e = min(ea*A_j, eb*B_j).
    //      warp w handles j = w and j = w + 16. ----
    {
        const float A0 = A_s[warp],      B0 = B_s[warp];
        const float A1 = A_s[warp + 16], B1 = B_s[warp + 16];
        float d0 = 0.0f, n0 = 0.0f, d1 = 0.0f, n1 = 0.0f;
        for (int p = lane; p < c; p += 32) {
            float x  = cx[p], r = crc[p];
            float ea = __expf( 10.0f * x);
            float eb = __expf(-10.0f * x);
            float e0 = fminf(ea * A0, eb * B0);
            float e1 = fminf(ea * A1, eb * B1);
            d0 += e0; n0 = fmaf(e0, r, n0);
            d1 += e1; n1 = fmaf(e1, r, n1);
        }
#pragma unroll
        for (int o = 16; o; o >>= 1) {
            d0 += __shfl_xor_sync(0xffffffffu, d0, o);
            n0 += __shfl_xor_sync(0xffffffffu, n0, o);
            d1 += __shfl_xor_sync(0xffffffffu, d1, o);
            n1 += __shfl_xor_sync(0xffffffffu, n1, o);
        }
        if (lane == 0) {
            corr_den[warp]      = d0; corr_num[warp]      = n0;
            corr_den[warp + 16] = d1; corr_num[warp + 16] = n1;
        }
    }
    __syncthreads();

    // ---- combine: den_j = A_j*Sea + corr, num_j = A_j*Src + corr ----
    if (tid < TK) {
        float Sea = 0.0f, Src = 0.0f;
#pragma unroll
        for (int w = 0; w < NW; w++) { Sea += pSea[w]; Src += pSrc[w]; }
        float A   = A_s[tid];
        float den = fmaf(A, Sea, corr_den[tid]);
        float num = fmaf(A, Src, corr_num[tid]);
        lbl_out[b * TK + tid] = num / den;
    }
}

extern "C" void kernel_launch(void* const* d_in, const int* in_sizes, int n_in,
                              void* d_out, int out_size)
{
    const float* scores    = (const float*)d_in[0];
    const int*   ref_class = (const int*)d_in[1];
    const int R = in_sizes[1];           // 8192
    const int B = in_sizes[0] / R;       // 128

    float* yk_out  = (float*)d_out;
    float* lbl_out = (float*)d_out + (size_t)B * TK;

    soft_argsort_topk_kernel<<<B, NT>>>(scores, ref_class, yk_out, lbl_out);
}